// round 14
// baseline (speedup 1.0000x reference)
#include <cuda_runtime.h>
#include <cstdint>

#define BB 8
#define NN 1024
#define DIN 64
#define HH 128
#define MSGD 128
#define LL 5
#define TGT 12
#define NLAYERS 3
#define ROWS (BB*NN)   // 8192

// ================= scratch =================
__device__ float    g_h   [ROWS*HH];
__device__ float    g_h0  [ROWS*HH];
__device__ uint32_t g_hh  [ROWS*64];       // bf16x2 hi plane of h (k-pairs)
__device__ uint32_t g_hl  [ROWS*64];       // bf16x2 lo plane
__device__ float    g_Ml  [ROWS*LL*MSGD];  // exact fp32 messages
__device__ float    g_aggP[2][ROWS*MSGD];  // w-split partials (2-way)
__device__ uint32_t g_msh [ROWS*64];       // bf16x2 split of aggsum
__device__ uint32_t g_msl [ROWS*64];
__device__ float    g_gi  [ROWS*3*HH];
__device__ float    g_gh  [ROWS*3*HH];
__device__ uint32_t g_Ahp [320*128];       // packed split weights [k2][o]
__device__ uint32_t g_Alp [320*128];
__device__ uint32_t g_Wihp[64*384];
__device__ uint32_t g_Wilp[64*384];
__device__ uint32_t g_Whhp[64*384];
__device__ uint32_t g_Whlp[64*384];
__device__ uint32_t g_lab [ROWS*NN/8];     // 4-bit labels, 8 per word
__device__ float    g_maskN[ROWS];
__device__ float    g_maskR[ROWS];

// ================= helpers =================
__device__ __forceinline__ uint32_t smem_u32(const void* p){
    uint32_t a;
    asm("{ .reg .u64 t; cvta.to.shared.u64 t, %1; cvt.u32.u64 %0, t; }" : "=r"(a) : "l"(p));
    return a;
}
__device__ __forceinline__ uint32_t packbf(float x0, float x1){
    uint32_t r; asm("cvt.rn.bf16x2.f32 %0, %1, %2;" : "=r"(r) : "f"(x1), "f"(x0)); return r;
}
__device__ __forceinline__ float bflo(uint32_t p){ return __uint_as_float(p << 16); }
__device__ __forceinline__ float bfhi(uint32_t p){ return __uint_as_float(p & 0xFFFF0000u); }

__device__ __forceinline__ void mma_bf16(float* d, const uint32_t* a, const uint32_t* b){
    asm volatile("mma.sync.aligned.m16n8k16.row.col.f32.bf16.bf16.f32 "
        "{%0,%1,%2,%3}, {%4,%5,%6,%7}, {%8,%9}, {%0,%1,%2,%3};"
        : "+f"(d[0]), "+f"(d[1]), "+f"(d[2]), "+f"(d[3])
        : "r"(a[0]), "r"(a[1]), "r"(a[2]), "r"(a[3]), "r"(b[0]), "r"(b[1]));
}
__device__ __forceinline__ void fma2(uint64_t& d, uint64_t a, uint64_t b){
    asm("fma.rn.f32x2 %0, %1, %2, %0;" : "+l"(d) : "l"(a), "l"(b));
}
__device__ __forceinline__ uint64_t rep2(float x){
    uint64_t r; uint32_t u = __float_as_uint(x);
    asm("mov.b64 %0, {%1, %1};" : "=l"(r) : "r"(u));
    return r;
}
#define CP_ASYNC16(dst, src) \
    asm volatile("cp.async.cg.shared.global [%0], [%1], 16;" :: "r"(dst), "l"(src))
#define CP_COMMIT() asm volatile("cp.async.commit_group;")
#define CP_WAIT0()  asm volatile("cp.async.wait_group 0;")

// ================= init (also zeroes out) =================
__global__ void k_init(const float* __restrict__ h_in, float* __restrict__ out)
{
    int n = blockIdx.x;
    int t = threadIdx.x;    // 128
    if (n == 0 && t < BB*TGT) out[t] = 0.f;
    float v = (t < DIN) ? h_in[n*DIN + t] : 0.f;
    g_h0[n*HH + t] = v;
    g_h [n*HH + t] = v;
    __shared__ float sv[128], sa[128], ss[128];
    sv[t] = v; sa[t] = fabsf(v); ss[t] = v;
    __syncthreads();
    for (int s = 64; s > 0; s >>= 1) {
        if (t < s) { sa[t] += sa[t+s]; ss[t] += ss[t+s]; }
        __syncthreads();
    }
    if (t < 64) {
        float x0 = sv[2*t], x1 = sv[2*t + 1];
        uint32_t hi = packbf(x0, x1);
        g_hh[n*64 + t] = hi;
        g_hl[n*64 + t] = packbf(x0 - bflo(hi), x1 - bfhi(hi));
    }
    if (t == 0) {
        g_maskN[n] = (sa[0] > 0.f) ? 1.f : 0.f;
        g_maskR[n] = (ss[0] > 0.f) ? 1.f : 0.f;
    }
}

// ================= fused setup: label packing + weight splitting =================
__device__ __forceinline__ void splitw_one(const float* W, uint32_t* dh, uint32_t* dl,
                                           int i, int nO)
{
    int k2 = i / nO, o = i - k2*nO;
    float w0 = W[(2*k2)*nO + o];
    float w1 = W[(2*k2 + 1)*nO + o];
    uint32_t hi = packbf(w0, w1);
    dh[i] = hi;
    dl[i] = packbf(w0 - bflo(hi), w1 - bfhi(hi));
}

__global__ void k_setup(const int* __restrict__ e, const float* __restrict__ A,
                        const float* __restrict__ Wi, const float* __restrict__ Wh)
{
    int blk = blockIdx.x;
    if (blk < 4096) {
        int i = blk*256 + threadIdx.x;
        const int4* e4 = (const int4*)e;
        int4 a = e4[i*2], b4 = e4[i*2 + 1];
        g_lab[i] = (uint32_t)a.x | ((uint32_t)a.y << 4) | ((uint32_t)a.z << 8) |
                   ((uint32_t)a.w << 12) | ((uint32_t)b4.x << 16) | ((uint32_t)b4.y << 20) |
                   ((uint32_t)b4.z << 24) | ((uint32_t)b4.w << 28);
    } else {
        int i = (blk - 4096)*256 + threadIdx.x;
        if (i < 40960) splitw_one(A, g_Ahp, g_Alp, i, 128);
        else if (i < 40960 + 24576) splitw_one(Wi, g_Wihp, g_Wilp, i - 40960, 384);
        else if (i < 40960 + 2*24576) splitw_one(Wh, g_Whhp, g_Whlp, i - 40960 - 24576, 384);
    }
}

// sum 2 agg partials -> packed split planes
__global__ void k_aggsum()
{
    int i = blockIdx.x*256 + threadIdx.x;   // ROWS*32 float4s
    const float4* p0 = (const float4*)g_aggP[0];
    const float4* p1 = (const float4*)g_aggP[1];
    float4 a = p0[i], b = p1[i];
    float4 s;
    s.x = a.x + b.x; s.y = a.y + b.y;
    s.z = a.z + b.z; s.w = a.w + b.w;
    uint32_t h0 = packbf(s.x, s.y), h1 = packbf(s.z, s.w);
    uint32_t l0 = packbf(s.x - bflo(h0), s.y - bfhi(h0));
    uint32_t l1 = packbf(s.z - bflo(h1), s.w - bfhi(h1));
    ((uint2*)g_msh)[i] = make_uint2(h0, h1);
    ((uint2*)g_msl)[i] = make_uint2(l0, l1);
}

// ================= bf16x3 gemm core =================
#define GEMM_SMEM ((2*2560 + 2*2560 + 2*2176 + 2*2176)*4)   // 75776 B

__device__ __forceinline__ void gemm_core(
    const uint32_t* __restrict__ Xh, const uint32_t* __restrict__ Xl,
    const uint32_t* __restrict__ Wph, const uint32_t* __restrict__ Wpl,
    const float* __restrict__ bias, float* __restrict__ C,
    int ldW, int ldC, int cBase, int row0, uint32_t* smu, int nChunk)
{
    uint32_t* sXh = smu;                 // [2][2560]  pitch 20
    uint32_t* sXl = smu + 5120;
    uint32_t* sWh = smu + 10240;         // [2][2176]  pitch 136
    uint32_t* sWl = smu + 14592;
    const uint32_t uXh = smem_u32(sXh), uXl = smem_u32(sXl);
    const uint32_t uWh = smem_u32(sWh), uWl = smem_u32(sWl);

    const int tid = threadIdx.x, lane = tid & 31, wid = tid >> 5;
    const int tq = lane & 3, gid = lane >> 2;
    const int vbase = (wid >> 1) << 5;
    const int obase = (wid & 1) << 6;

    float acc[2][8][4];
#pragma unroll
    for (int i = 0; i < 2; i++)
#pragma unroll
        for (int j = 0; j < 8; j++)
#pragma unroll
            for (int k = 0; k < 4; k++) acc[i][j][k] = 0.f;

    auto stage = [&](int c) {
        int buf = c & 1; int k02 = c << 4;
#pragma unroll
        for (int r = 0; r < 2; r++) {
            int idx = (r << 8) + tid; int v = idx >> 2, q = idx & 3;
            size_t off = (size_t)(row0 + v)*64 + k02 + (q << 2);
            uint32_t d = (uint32_t)(buf*2560 + v*20 + (q << 2))*4;
            CP_ASYNC16(uXh + d, Xh + off);
            CP_ASYNC16(uXl + d, Xl + off);
        }
#pragma unroll
        for (int r = 0; r < 2; r++) {
            int idx = (r << 8) + tid; int k2 = idx >> 5, o4 = idx & 31;
            size_t off = (size_t)(k02 + k2)*ldW + (o4 << 2);
            uint32_t d = (uint32_t)(buf*2176 + k2*136 + (o4 << 2))*4;
            CP_ASYNC16(uWh + d, Wph + off);
            CP_ASYNC16(uWl + d, Wpl + off);
        }
        CP_COMMIT();
    };

    stage(0);
    for (int c = 0; c < nChunk; c++) {
        CP_WAIT0();
        __syncthreads();
        if (c < nChunk - 1) stage(c + 1);
        int buf = c & 1;
        const uint32_t* bXh = sXh + buf*2560;
        const uint32_t* bXl = sXl + buf*2560;
        const uint32_t* bWh = sWh + buf*2176;
        const uint32_t* bWl = sWl + buf*2176;
#pragma unroll
        for (int h = 0; h < 2; h++) {
            int kk2 = (h << 3) + tq;
            uint32_t ah[2][4], al[2][4];
#pragma unroll
            for (int mt = 0; mt < 2; mt++) {
                int vr = vbase + (mt << 4) + gid;
                ah[mt][0] = bXh[vr*20 + kk2];       ah[mt][1] = bXh[(vr+8)*20 + kk2];
                ah[mt][2] = bXh[vr*20 + kk2 + 4];   ah[mt][3] = bXh[(vr+8)*20 + kk2 + 4];
                al[mt][0] = bXl[vr*20 + kk2];       al[mt][1] = bXl[(vr+8)*20 + kk2];
                al[mt][2] = bXl[vr*20 + kk2 + 4];   al[mt][3] = bXl[(vr+8)*20 + kk2 + 4];
            }
#pragma unroll
            for (int nt = 0; nt < 8; nt++) {
                int o = obase + (nt << 3) + gid;
                uint32_t bh2[2] = { bWh[kk2*136 + o], bWh[(kk2+4)*136 + o] };
                uint32_t bl2[2] = { bWl[kk2*136 + o], bWl[(kk2+4)*136 + o] };
                mma_bf16(acc[0][nt], ah[0], bh2);
                mma_bf16(acc[0][nt], ah[0], bl2);
                mma_bf16(acc[0][nt], al[0], bh2);
                mma_bf16(acc[1][nt], ah[1], bh2);
                mma_bf16(acc[1][nt], ah[1], bl2);
                mma_bf16(acc[1][nt], al[1], bh2);
            }
        }
        __syncthreads();
    }

#pragma unroll
    for (int mt = 0; mt < 2; mt++)
#pragma unroll
        for (int nt = 0; nt < 8; nt++) {
            int row = row0 + vbase + (mt << 4) + gid;
            int col = cBase + obase + (nt << 3) + (tq << 1);
            float b0 = 0.f, b1 = 0.f;
            if (bias) { b0 = bias[col - cBase]; b1 = bias[col - cBase + 1]; }
            *(float2*)&C[(size_t)row*ldC + col] =
                make_float2(acc[mt][nt][0] + b0, acc[mt][nt][1] + b1);
            *(float2*)&C[(size_t)(row + 8)*ldC + col] =
                make_float2(acc[mt][nt][2] + b0, acc[mt][nt][3] + b1);
        }
}

// merged Ml-gemm (y 0..4) + Wh-gemm (y 5..7)
__global__ void __launch_bounds__(256, 2) k_gemmA(const float* __restrict__ bh, int nChunk)
{
    extern __shared__ uint32_t smu[];
    int y = blockIdx.y;
    int row0 = blockIdx.x << 7;
    if (y < 5) {
        gemm_core(g_hh, g_hl, g_Ahp + y*64*128, g_Alp + y*64*128,
                  nullptr, g_Ml, 128, 640, y << 7, row0, smu, nChunk);
    } else {
        int yy = y - 5;
        gemm_core(g_hh, g_hl, g_Whhp + (yy << 7), g_Whlp + (yy << 7),
                  bh + (yy << 7), g_gh, 384, 384, yy << 7, row0, smu, nChunk);
    }
}

__global__ void __launch_bounds__(256, 2) k_gemmWi(const float* __restrict__ bi)
{
    extern __shared__ uint32_t smu[];
    int y = blockIdx.y;
    int row0 = blockIdx.x << 7;
    gemm_core(g_msh, g_msl, g_Wihp + (y << 7), g_Wilp + (y << 7),
              bi + (y << 7), g_gi, 384, 384, y << 7, row0, smu, 4);
}

// ================= exact fp32 gather aggregation =================
// R12-best geometry (chunk 16, 2 CTAs/SM), w-split 2 -> grid (128, 2).
// Per buffer (45056 B): [0,40960) sM (16 rows x 640 f), [40960,45056) sG.
// Labels at 90112: 64 v x 64 words = 16 KB. Total 106496 B.
#define AGG_BUF  11264                 // floats per buffer
#define AGG_SMEM 106496

__global__ void __launch_bounds__(256, 2) k_agg(const float* __restrict__ g)
{
    extern __shared__ float sm[];
    const uint32_t base_u = smem_u32(sm);

    const int tid = threadIdx.x, lane = tid & 31, wid = tid >> 5;
    const int b  = blockIdx.x >> 4;
    const int v0 = (blockIdx.x & 15) << 6;
    const int wbeg = blockIdx.y << 9;   // 512 w per split

    uint64_t acc2[8][2];
#pragma unroll
    for (int i = 0; i < 8; i++) { acc2[i][0] = 0ull; acc2[i][1] = 0ull; }

    // preload labels: 64 v x 64 words = 1024 float4 transfers
    {
#pragma unroll
        for (int r = 0; r < 4; r++) {
            int idx = (r << 8) + tid;
            int v = idx >> 4, q = idx & 15;
            CP_ASYNC16(base_u + 90112 + ((v << 6) + (q << 2))*4,
                       g_lab + (size_t)((b << 10) + v0 + v)*128 + (wbeg >> 3) + (q << 2));
        }
    }

    auto stage = [&](int c) {
        int w0 = wbeg + (c << 4);
        int buf = c & 1;
        const float* src = g_Ml + (size_t)((b << 10) + w0)*640;
#pragma unroll
        for (int r = 0; r < 10; r++)
            CP_ASYNC16(base_u + buf*45056 + (((r << 8) + tid) << 4),
                       src + (((r << 8) + tid) << 2));
        {   // g: 64 v x 16 w = 256 float4, 1 per thread
            int v = tid >> 2, q = tid & 3;
            CP_ASYNC16(base_u + buf*45056 + 40960 + ((v << 4) + (q << 2))*4,
                       g + ((size_t)((b << 10) + v0 + v) << 10) + w0 + (q << 2));
        }
        CP_COMMIT();
    };

    stage(0);
    const uint32_t* sLabA = (const uint32_t*)(sm + 22528);

    for (int c = 0; c < 32; c++) {
        CP_WAIT0();
        __syncthreads();
        if (c < 31) stage(c + 1);
        int buf = c & 1;
        const ulonglong2* sM2 = (const ulonglong2*)(sm + buf*AGG_BUF);
        const float4*     sG4 = (const float4*)(sm + buf*AGG_BUF + 10240);
#pragma unroll
        for (int i = 0; i < 8; i++) {
            int v = (wid << 3) + i;
            uint32_t lw0 = sLabA[(v << 6) + (c << 1)];
            uint32_t lw1 = sLabA[(v << 6) + (c << 1) + 1];
            float4 G0 = sG4[(v << 2)];
            float4 G1 = sG4[(v << 2) + 1];
            float4 G2 = sG4[(v << 2) + 2];
            float4 G3 = sG4[(v << 2) + 3];
            float gw[16] = {G0.x,G0.y,G0.z,G0.w, G1.x,G1.y,G1.z,G1.w,
                            G2.x,G2.y,G2.z,G2.w, G3.x,G3.y,G3.z,G3.w};
#pragma unroll
            for (int w = 0; w < 16; w++) {
                uint32_t lw = (w < 8) ? lw0 : lw1;
                uint32_t off = ((lw >> ((w & 7) << 2)) & 0xFu) << 5;
                ulonglong2 m2 = sM2[w*160 + off + lane];
                uint64_t gp = rep2(gw[w]);
                fma2(acc2[i][0], m2.x, gp);
                fma2(acc2[i][1], m2.y, gp);
            }
        }
        __syncthreads();
    }

    float* dst = g_aggP[blockIdx.y];
#pragma unroll
    for (int i = 0; i < 8; i++) {
        int row = (b << 10) + v0 + (wid << 3) + i;
        ulonglong2 o; o.x = acc2[i][0]; o.y = acc2[i][1];
        *(ulonglong2*)&dst[(size_t)row*128 + (lane << 2)] = o;
    }
}

// ================= GRU (pairs; writes h + packed planes) =================
__global__ void k_gru()
{
    int idx = blockIdx.x*256 + threadIdx.x;   // ROWS*64
    int n = idx >> 6;
    int c2 = idx & 63;
    int base = n*384 + (c2 << 1);
    float2 ir = *(float2*)&g_gi[base];
    float2 iz = *(float2*)&g_gi[base + 128];
    float2 in_ = *(float2*)&g_gi[base + 256];
    float2 hr = *(float2*)&g_gh[base];
    float2 hz = *(float2*)&g_gh[base + 128];
    float2 hn = *(float2*)&g_gh[base + 256];
    float2 h2 = *(float2*)&g_h[(n << 7) + (c2 << 1)];
    float mask = g_maskN[n];

    float r0 = 1.f/(1.f + __expf(-(ir.x + hr.x)));
    float z0 = 1.f/(1.f + __expf(-(iz.x + hz.x)));
    float n0 = tanhf(in_.x + r0*hn.x);
    float v0 = ((1.f - z0)*n0 + z0*h2.x) * mask;
    float r1 = 1.f/(1.f + __expf(-(ir.y + hr.y)));
    float z1 = 1.f/(1.f + __expf(-(iz.y + hz.y)));
    float n1 = tanhf(in_.y + r1*hn.y);
    float v1 = ((1.f - z1)*n1 + z1*h2.y) * mask;

    *(float2*)&g_h[(n << 7) + (c2 << 1)] = make_float2(v0, v1);
    uint32_t hi = packbf(v0, v1);
    g_hh[idx] = hi;
    g_hl[idx] = packbf(v0 - bflo(hi), v1 - bfhi(hi));
}

// ================= readout: 8 nodes per block, weights cached in smem =================
__global__ void __launch_bounds__(128) k_readout(
    const float* __restrict__ Wg, const float* __restrict__ bg,
    const float* __restrict__ Wo, const float* __restrict__ bo,
    float* __restrict__ out)
{
    __shared__ float sWg[256*TGT];   // 12 KB
    __shared__ float sWo[128*TGT];   // 6 KB
    __shared__ float red[24][128];
    __shared__ float s2[24];
    int t = threadIdx.x;             // 128

    for (int i = t; i < 256*TGT; i += 128) sWg[i] = Wg[i];
    for (int i = t; i < 128*TGT; i += 128) sWo[i] = Wo[i];
    __syncthreads();

    int n0 = blockIdx.x << 3;
    for (int nn = 0; nn < 8; nn++) {
        int n = n0 + nn;
        float hT = g_h [n*HH + t];
        float h0 = g_h0[n*HH + t];
#pragma unroll
        for (int j = 0; j < TGT; j++) {
            red[j][t]      = hT*sWg[t*TGT + j] + h0*sWg[(HH + t)*TGT + j];
            red[12 + j][t] = hT*sWo[t*TGT + j];
        }
        __syncthreads();
        if (t < 24) {
            float s = 0.f;
            for (int i = 0; i < 128; i++) s += red[t][i];
            s2[t] = s;
        }
        __syncthreads();
        if (t < TGT) {
            float gate = 1.f/(1.f + __expf(-(s2[t] + bg[t])));
            float val  = gate*(s2[12 + t] + bo[t]) * g_maskR[n];
            atomicAdd(&out[(n >> 10)*TGT + t], val);
        }
        __syncthreads();
    }
}

// ================= launch =================
extern "C" void kernel_launch(void* const* d_in, const int* in_sizes, int n_in,
                              void* d_out, int out_size)
{
    const float* g    = (const float*)d_in[0];
    const float* h_in = (const float*)d_in[1];
    const int*   e    = (const int*)  d_in[2];
    const float* A    = (const float*)d_in[3];
    const float* Wi   = (const float*)d_in[4];
    const float* Wh   = (const float*)d_in[5];
    const float* bi   = (const float*)d_in[6];
    const float* bh   = (const float*)d_in[7];
    const float* Wg   = (const float*)d_in[8];
    const float* bg   = (const float*)d_in[9];
    const float* Wo   = (const float*)d_in[10];
    const float* bo   = (const float*)d_in[11];
    float* out = (float*)d_out;

    static int attr_set = 0;
    if (!attr_set) {
        cudaFuncSetAttribute(k_gemmA,  cudaFuncAttributeMaxDynamicSharedMemorySize, GEMM_SMEM);
        cudaFuncSetAttribute(k_gemmWi, cudaFuncAttributeMaxDynamicSharedMemorySize, GEMM_SMEM);
        cudaFuncSetAttribute(k_agg,    cudaFuncAttributeMaxDynamicSharedMemorySize, AGG_SMEM);
        attr_set = 1;
    }

    // Launch order: k_agg is the 4th launch -> the one ncu captures.
    k_init<<<ROWS, 128>>>(h_in, out);                      // 1
    k_setup<<<4096 + 352, 256>>>(e, A, Wi, Wh);            // 2

    for (int layer = 0; layer < NLAYERS; layer++) {
        k_gemmA<<<dim3(64, 8), 256, GEMM_SMEM>>>(bh, layer == 0 ? 2 : 4);  // 3
        k_agg<<<dim3(128, 2), 256, AGG_SMEM>>>(g);                         // 4 <- profiled
        k_aggsum<<<ROWS*32/256, 256>>>();
        k_gemmWi<<<dim3(64, 3), 256, GEMM_SMEM>>>(bi);
        k_gru<<<ROWS*64/256, 256>>>();
    }

    k_readout<<<ROWS/8, 128>>>(Wg, bg, Wo, bo, out);
}

// round 15
// speedup vs baseline: 1.0157x; 1.0157x over previous
#include <cuda_runtime.h>
#include <cstdint>

#define BB 8
#define NN 1024
#define DIN 64
#define HH 128
#define MSGD 128
#define LL 5
#define TGT 12
#define NLAYERS 3
#define ROWS (BB*NN)   // 8192

// ================= scratch =================
__device__ float    g_h   [ROWS*HH];
__device__ float    g_h0  [ROWS*HH];
__device__ uint32_t g_hh  [ROWS*64];       // bf16x2 hi plane of h (k-pairs)
__device__ uint32_t g_hl  [ROWS*64];       // bf16x2 lo plane
__device__ float    g_Ml  [ROWS*LL*MSGD];  // exact fp32 messages
__device__ float    g_aggP[2][ROWS*MSGD];  // w-split partials (2-way)
__device__ uint32_t g_msh [ROWS*64];       // bf16x2 split of aggsum
__device__ uint32_t g_msl [ROWS*64];
__device__ float    g_gi  [ROWS*3*HH];
__device__ float    g_gh  [ROWS*3*HH];
__device__ uint32_t g_Ahp [320*128];       // packed split weights [k2][o]
__device__ uint32_t g_Alp [320*128];
__device__ uint32_t g_Wihp[64*384];
__device__ uint32_t g_Wilp[64*384];
__device__ uint32_t g_Whhp[64*384];
__device__ uint32_t g_Whlp[64*384];
__device__ uint32_t g_lab [ROWS*NN/8];     // 4-bit labels, 8 per word
__device__ float    g_maskN[ROWS];
__device__ float    g_maskR[ROWS];

// ================= helpers =================
__device__ __forceinline__ uint32_t smem_u32(const void* p){
    uint32_t a;
    asm("{ .reg .u64 t; cvta.to.shared.u64 t, %1; cvt.u32.u64 %0, t; }" : "=r"(a) : "l"(p));
    return a;
}
__device__ __forceinline__ uint32_t packbf(float x0, float x1){
    uint32_t r; asm("cvt.rn.bf16x2.f32 %0, %1, %2;" : "=r"(r) : "f"(x1), "f"(x0)); return r;
}
__device__ __forceinline__ float bflo(uint32_t p){ return __uint_as_float(p << 16); }
__device__ __forceinline__ float bfhi(uint32_t p){ return __uint_as_float(p & 0xFFFF0000u); }

__device__ __forceinline__ void mma_bf16(float* d, const uint32_t* a, const uint32_t* b){
    asm volatile("mma.sync.aligned.m16n8k16.row.col.f32.bf16.bf16.f32 "
        "{%0,%1,%2,%3}, {%4,%5,%6,%7}, {%8,%9}, {%0,%1,%2,%3};"
        : "+f"(d[0]), "+f"(d[1]), "+f"(d[2]), "+f"(d[3])
        : "r"(a[0]), "r"(a[1]), "r"(a[2]), "r"(a[3]), "r"(b[0]), "r"(b[1]));
}
__device__ __forceinline__ void fma2(uint64_t& d, uint64_t a, uint64_t b){
    asm("fma.rn.f32x2 %0, %1, %2, %0;" : "+l"(d) : "l"(a), "l"(b));
}
__device__ __forceinline__ uint64_t rep2(float x){
    uint64_t r; uint32_t u = __float_as_uint(x);
    asm("mov.b64 %0, {%1, %1};" : "=l"(r) : "r"(u));
    return r;
}
#define CP_ASYNC16(dst, src) \
    asm volatile("cp.async.cg.shared.global [%0], [%1], 16;" :: "r"(dst), "l"(src))
#define CP_COMMIT() asm volatile("cp.async.commit_group;")
#define CP_WAIT0()  asm volatile("cp.async.wait_group 0;")

// ================= init (also zeroes out) =================
__global__ void k_init(const float* __restrict__ h_in, float* __restrict__ out)
{
    int n = blockIdx.x;
    int t = threadIdx.x;    // 128
    if (n == 0 && t < BB*TGT) out[t] = 0.f;
    float v = (t < DIN) ? h_in[n*DIN + t] : 0.f;
    g_h0[n*HH + t] = v;
    g_h [n*HH + t] = v;
    __shared__ float sv[128], sa[128], ss[128];
    sv[t] = v; sa[t] = fabsf(v); ss[t] = v;
    __syncthreads();
    for (int s = 64; s > 0; s >>= 1) {
        if (t < s) { sa[t] += sa[t+s]; ss[t] += ss[t+s]; }
        __syncthreads();
    }
    if (t < 64) {
        float x0 = sv[2*t], x1 = sv[2*t + 1];
        uint32_t hi = packbf(x0, x1);
        g_hh[n*64 + t] = hi;
        g_hl[n*64 + t] = packbf(x0 - bflo(hi), x1 - bfhi(hi));
    }
    if (t == 0) {
        g_maskN[n] = (sa[0] > 0.f) ? 1.f : 0.f;
        g_maskR[n] = (ss[0] > 0.f) ? 1.f : 0.f;
    }
}

// ================= fused setup: label packing + weight splitting =================
__device__ __forceinline__ void splitw_one(const float* W, uint32_t* dh, uint32_t* dl,
                                           int i, int nO)
{
    int k2 = i / nO, o = i - k2*nO;
    float w0 = W[(2*k2)*nO + o];
    float w1 = W[(2*k2 + 1)*nO + o];
    uint32_t hi = packbf(w0, w1);
    dh[i] = hi;
    dl[i] = packbf(w0 - bflo(hi), w1 - bfhi(hi));
}

__global__ void k_setup(const int* __restrict__ e, const float* __restrict__ A,
                        const float* __restrict__ Wi, const float* __restrict__ Wh)
{
    int blk = blockIdx.x;
    if (blk < 4096) {
        int i = blk*256 + threadIdx.x;
        const int4* e4 = (const int4*)e;
        int4 a = e4[i*2], b4 = e4[i*2 + 1];
        g_lab[i] = (uint32_t)a.x | ((uint32_t)a.y << 4) | ((uint32_t)a.z << 8) |
                   ((uint32_t)a.w << 12) | ((uint32_t)b4.x << 16) | ((uint32_t)b4.y << 20) |
                   ((uint32_t)b4.z << 24) | ((uint32_t)b4.w << 28);
    } else {
        int i = (blk - 4096)*256 + threadIdx.x;
        if (i < 40960) splitw_one(A, g_Ahp, g_Alp, i, 128);
        else if (i < 40960 + 24576) splitw_one(Wi, g_Wihp, g_Wilp, i - 40960, 384);
        else if (i < 40960 + 2*24576) splitw_one(Wh, g_Whhp, g_Whlp, i - 40960 - 24576, 384);
    }
}

// sum 2 agg partials -> packed split planes
__global__ void k_aggsum()
{
    int i = blockIdx.x*256 + threadIdx.x;   // ROWS*32 float4s
    const float4* p0 = (const float4*)g_aggP[0];
    const float4* p1 = (const float4*)g_aggP[1];
    float4 a = p0[i], b = p1[i];
    float4 s;
    s.x = a.x + b.x; s.y = a.y + b.y;
    s.z = a.z + b.z; s.w = a.w + b.w;
    uint32_t h0 = packbf(s.x, s.y), h1 = packbf(s.z, s.w);
    uint32_t l0 = packbf(s.x - bflo(h0), s.y - bfhi(h0));
    uint32_t l1 = packbf(s.z - bflo(h1), s.w - bfhi(h1));
    ((uint2*)g_msh)[i] = make_uint2(h0, h1);
    ((uint2*)g_msl)[i] = make_uint2(l0, l1);
}

// ================= bf16x3 gemm core =================
#define GEMM_SMEM ((2*2560 + 2*2560 + 2*2176 + 2*2176)*4)   // 75776 B

__device__ __forceinline__ void gemm_core(
    const uint32_t* __restrict__ Xh, const uint32_t* __restrict__ Xl,
    const uint32_t* __restrict__ Wph, const uint32_t* __restrict__ Wpl,
    const float* __restrict__ bias, float* __restrict__ C,
    int ldW, int ldC, int cBase, int row0, uint32_t* smu, int nChunk)
{
    uint32_t* sXh = smu;                 // [2][2560]  pitch 20
    uint32_t* sXl = smu + 5120;
    uint32_t* sWh = smu + 10240;         // [2][2176]  pitch 136
    uint32_t* sWl = smu + 14592;
    const uint32_t uXh = smem_u32(sXh), uXl = smem_u32(sXl);
    const uint32_t uWh = smem_u32(sWh), uWl = smem_u32(sWl);

    const int tid = threadIdx.x, lane = tid & 31, wid = tid >> 5;
    const int tq = lane & 3, gid = lane >> 2;
    const int vbase = (wid >> 1) << 5;
    const int obase = (wid & 1) << 6;

    float acc[2][8][4];
#pragma unroll
    for (int i = 0; i < 2; i++)
#pragma unroll
        for (int j = 0; j < 8; j++)
#pragma unroll
            for (int k = 0; k < 4; k++) acc[i][j][k] = 0.f;

    auto stage = [&](int c) {
        int buf = c & 1; int k02 = c << 4;
#pragma unroll
        for (int r = 0; r < 2; r++) {
            int idx = (r << 8) + tid; int v = idx >> 2, q = idx & 3;
            size_t off = (size_t)(row0 + v)*64 + k02 + (q << 2);
            uint32_t d = (uint32_t)(buf*2560 + v*20 + (q << 2))*4;
            CP_ASYNC16(uXh + d, Xh + off);
            CP_ASYNC16(uXl + d, Xl + off);
        }
#pragma unroll
        for (int r = 0; r < 2; r++) {
            int idx = (r << 8) + tid; int k2 = idx >> 5, o4 = idx & 31;
            size_t off = (size_t)(k02 + k2)*ldW + (o4 << 2);
            uint32_t d = (uint32_t)(buf*2176 + k2*136 + (o4 << 2))*4;
            CP_ASYNC16(uWh + d, Wph + off);
            CP_ASYNC16(uWl + d, Wpl + off);
        }
        CP_COMMIT();
    };

    stage(0);
    for (int c = 0; c < nChunk; c++) {
        CP_WAIT0();
        __syncthreads();
        if (c < nChunk - 1) stage(c + 1);
        int buf = c & 1;
        const uint32_t* bXh = sXh + buf*2560;
        const uint32_t* bXl = sXl + buf*2560;
        const uint32_t* bWh = sWh + buf*2176;
        const uint32_t* bWl = sWl + buf*2176;
#pragma unroll
        for (int h = 0; h < 2; h++) {
            int kk2 = (h << 3) + tq;
            uint32_t ah[2][4], al[2][4];
#pragma unroll
            for (int mt = 0; mt < 2; mt++) {
                int vr = vbase + (mt << 4) + gid;
                ah[mt][0] = bXh[vr*20 + kk2];       ah[mt][1] = bXh[(vr+8)*20 + kk2];
                ah[mt][2] = bXh[vr*20 + kk2 + 4];   ah[mt][3] = bXh[(vr+8)*20 + kk2 + 4];
                al[mt][0] = bXl[vr*20 + kk2];       al[mt][1] = bXl[(vr+8)*20 + kk2];
                al[mt][2] = bXl[vr*20 + kk2 + 4];   al[mt][3] = bXl[(vr+8)*20 + kk2 + 4];
            }
#pragma unroll
            for (int nt = 0; nt < 8; nt++) {
                int o = obase + (nt << 3) + gid;
                uint32_t bh2[2] = { bWh[kk2*136 + o], bWh[(kk2+4)*136 + o] };
                uint32_t bl2[2] = { bWl[kk2*136 + o], bWl[(kk2+4)*136 + o] };
                mma_bf16(acc[0][nt], ah[0], bh2);
                mma_bf16(acc[0][nt], ah[0], bl2);
                mma_bf16(acc[0][nt], al[0], bh2);
                mma_bf16(acc[1][nt], ah[1], bh2);
                mma_bf16(acc[1][nt], ah[1], bl2);
                mma_bf16(acc[1][nt], al[1], bh2);
            }
        }
        __syncthreads();
    }

#pragma unroll
    for (int mt = 0; mt < 2; mt++)
#pragma unroll
        for (int nt = 0; nt < 8; nt++) {
            int row = row0 + vbase + (mt << 4) + gid;
            int col = cBase + obase + (nt << 3) + (tq << 1);
            float b0 = 0.f, b1 = 0.f;
            if (bias) { b0 = bias[col - cBase]; b1 = bias[col - cBase + 1]; }
            *(float2*)&C[(size_t)row*ldC + col] =
                make_float2(acc[mt][nt][0] + b0, acc[mt][nt][1] + b1);
            *(float2*)&C[(size_t)(row + 8)*ldC + col] =
                make_float2(acc[mt][nt][2] + b0, acc[mt][nt][3] + b1);
        }
}

// merged Ml-gemm (y 0..4) + Wh-gemm (y 5..7)
__global__ void __launch_bounds__(256, 2) k_gemmA(const float* __restrict__ bh, int nChunk)
{
    extern __shared__ uint32_t smu[];
    int y = blockIdx.y;
    int row0 = blockIdx.x << 7;
    if (y < 5) {
        gemm_core(g_hh, g_hl, g_Ahp + y*64*128, g_Alp + y*64*128,
                  nullptr, g_Ml, 128, 640, y << 7, row0, smu, nChunk);
    } else {
        int yy = y - 5;
        gemm_core(g_hh, g_hl, g_Whhp + (yy << 7), g_Whlp + (yy << 7),
                  bh + (yy << 7), g_gh, 384, 384, yy << 7, row0, smu, nChunk);
    }
}

__global__ void __launch_bounds__(256, 2) k_gemmWi(const float* __restrict__ bi)
{
    extern __shared__ uint32_t smu[];
    int y = blockIdx.y;
    int row0 = blockIdx.x << 7;
    gemm_core(g_msh, g_msl, g_Wihp + (y << 7), g_Wilp + (y << 7),
              bi + (y << 7), g_gi, 384, 384, y << 7, row0, smu, 4);
}

// ================= exact fp32 gather aggregation =================
// Measured-best geometry (chunk 16, 2 CTAs/SM), w-split 2 -> grid (128, 2).
// Per buffer (45056 B): [0,40960) sM (16 rows x 640 f), [40960,45056) sG.
// Labels at 90112: 64 v x 64 words = 16 KB. Total 106496 B.
#define AGG_BUF  11264                 // floats per buffer
#define AGG_SMEM 106496

__global__ void __launch_bounds__(256, 2) k_agg(const float* __restrict__ g)
{
    extern __shared__ float sm[];
    const uint32_t base_u = smem_u32(sm);

    const int tid = threadIdx.x, lane = tid & 31, wid = tid >> 5;
    const int b  = blockIdx.x >> 4;
    const int v0 = (blockIdx.x & 15) << 6;
    const int wbeg = blockIdx.y << 9;   // 512 w per split

    uint64_t acc2[8][2];
#pragma unroll
    for (int i = 0; i < 8; i++) { acc2[i][0] = 0ull; acc2[i][1] = 0ull; }

    // preload labels: 64 v x 64 words = 1024 float4 transfers
    {
#pragma unroll
        for (int r = 0; r < 4; r++) {
            int idx = (r << 8) + tid;
            int v = idx >> 4, q = idx & 15;
            CP_ASYNC16(base_u + 90112 + ((v << 6) + (q << 2))*4,
                       g_lab + (size_t)((b << 10) + v0 + v)*128 + (wbeg >> 3) + (q << 2));
        }
    }

    auto stage = [&](int c) {
        int w0 = wbeg + (c << 4);
        int buf = c & 1;
        const float* src = g_Ml + (size_t)((b << 10) + w0)*640;
#pragma unroll
        for (int r = 0; r < 10; r++)
            CP_ASYNC16(base_u + buf*45056 + (((r << 8) + tid) << 4),
                       src + (((r << 8) + tid) << 2));
        {   // g: 64 v x 16 w = 256 float4, 1 per thread
            int v = tid >> 2, q = tid & 3;
            CP_ASYNC16(base_u + buf*45056 + 40960 + ((v << 4) + (q << 2))*4,
                       g + ((size_t)((b << 10) + v0 + v) << 10) + w0 + (q << 2));
        }
        CP_COMMIT();
    };

    stage(0);
    const uint32_t* sLabA = (const uint32_t*)(sm + 22528);

    for (int c = 0; c < 32; c++) {
        CP_WAIT0();
        __syncthreads();
        if (c < 31) stage(c + 1);
        int buf = c & 1;
        const ulonglong2* sM2 = (const ulonglong2*)(sm + buf*AGG_BUF);
        const float4*     sG4 = (const float4*)(sm + buf*AGG_BUF + 10240);
#pragma unroll
        for (int i = 0; i < 8; i++) {
            int v = (wid << 3) + i;
            uint32_t lw0 = sLabA[(v << 6) + (c << 1)];
            uint32_t lw1 = sLabA[(v << 6) + (c << 1) + 1];
            float4 G0 = sG4[(v << 2)];
            float4 G1 = sG4[(v << 2) + 1];
            float4 G2 = sG4[(v << 2) + 2];
            float4 G3 = sG4[(v << 2) + 3];
            float gw[16] = {G0.x,G0.y,G0.z,G0.w, G1.x,G1.y,G1.z,G1.w,
                            G2.x,G2.y,G2.z,G2.w, G3.x,G3.y,G3.z,G3.w};
#pragma unroll
            for (int w = 0; w < 16; w++) {
                uint32_t lw = (w < 8) ? lw0 : lw1;
                uint32_t off = ((lw >> ((w & 7) << 2)) & 0xFu) << 5;
                ulonglong2 m2 = sM2[w*160 + off + lane];
                uint64_t gp = rep2(gw[w]);
                fma2(acc2[i][0], m2.x, gp);
                fma2(acc2[i][1], m2.y, gp);
            }
        }
        __syncthreads();
    }

    float* dst = g_aggP[blockIdx.y];
#pragma unroll
    for (int i = 0; i < 8; i++) {
        int row = (b << 10) + v0 + (wid << 3) + i;
        ulonglong2 o; o.x = acc2[i][0]; o.y = acc2[i][1];
        *(ulonglong2*)&dst[(size_t)row*128 + (lane << 2)] = o;
    }
}

// ================= GRU (pairs; writes h + packed planes) =================
__global__ void k_gru()
{
    int idx = blockIdx.x*256 + threadIdx.x;   // ROWS*64
    int n = idx >> 6;
    int c2 = idx & 63;
    int base = n*384 + (c2 << 1);
    float2 ir = *(float2*)&g_gi[base];
    float2 iz = *(float2*)&g_gi[base + 128];
    float2 in_ = *(float2*)&g_gi[base + 256];
    float2 hr = *(float2*)&g_gh[base];
    float2 hz = *(float2*)&g_gh[base + 128];
    float2 hn = *(float2*)&g_gh[base + 256];
    float2 h2 = *(float2*)&g_h[(n << 7) + (c2 << 1)];
    float mask = g_maskN[n];

    float r0 = 1.f/(1.f + __expf(-(ir.x + hr.x)));
    float z0 = 1.f/(1.f + __expf(-(iz.x + hz.x)));
    float n0 = tanhf(in_.x + r0*hn.x);
    float v0 = ((1.f - z0)*n0 + z0*h2.x) * mask;
    float r1 = 1.f/(1.f + __expf(-(ir.y + hr.y)));
    float z1 = 1.f/(1.f + __expf(-(iz.y + hz.y)));
    float n1 = tanhf(in_.y + r1*hn.y);
    float v1 = ((1.f - z1)*n1 + z1*h2.y) * mask;

    *(float2*)&g_h[(n << 7) + (c2 << 1)] = make_float2(v0, v1);
    uint32_t hi = packbf(v0, v1);
    g_hh[idx] = hi;
    g_hl[idx] = packbf(v0 - bflo(hi), v1 - bfhi(hi));
}

// ================= readout (R12 version — measured best) =================
__global__ void k_readout(const float* __restrict__ Wg, const float* __restrict__ bg,
                          const float* __restrict__ Wo, const float* __restrict__ bo,
                          float* __restrict__ out)
{
    int n = blockIdx.x;
    int t = threadIdx.x;
    float hT = g_h [n*HH + t];
    float h0 = g_h0[n*HH + t];
    __shared__ float red[24][128];
    __shared__ float s2[24];
#pragma unroll
    for (int j = 0; j < TGT; j++) {
        red[j][t]      = hT*Wg[t*TGT + j] + h0*Wg[(HH + t)*TGT + j];
        red[12 + j][t] = hT*Wo[t*TGT + j];
    }
    __syncthreads();
    if (t < 24) {
        float s = 0.f;
        for (int i = 0; i < 128; i++) s += red[t][i];
        s2[t] = s;
    }
    __syncthreads();
    if (t < TGT) {
        float gate = 1.f/(1.f + __expf(-(s2[t] + bg[t])));
        float val  = gate*(s2[12 + t] + bo[t]) * g_maskR[n];
        atomicAdd(&out[(n >> 10)*TGT + t], val);
    }
}

// ================= launch =================
extern "C" void kernel_launch(void* const* d_in, const int* in_sizes, int n_in,
                              void* d_out, int out_size)
{
    const float* g    = (const float*)d_in[0];
    const float* h_in = (const float*)d_in[1];
    const int*   e    = (const int*)  d_in[2];
    const float* A    = (const float*)d_in[3];
    const float* Wi   = (const float*)d_in[4];
    const float* Wh   = (const float*)d_in[5];
    const float* bi   = (const float*)d_in[6];
    const float* bh   = (const float*)d_in[7];
    const float* Wg   = (const float*)d_in[8];
    const float* bg   = (const float*)d_in[9];
    const float* Wo   = (const float*)d_in[10];
    const float* bo   = (const float*)d_in[11];
    float* out = (float*)d_out;

    static int attr_set = 0;
    if (!attr_set) {
        cudaFuncSetAttribute(k_gemmA,  cudaFuncAttributeMaxDynamicSharedMemorySize, GEMM_SMEM);
        cudaFuncSetAttribute(k_gemmWi, cudaFuncAttributeMaxDynamicSharedMemorySize, GEMM_SMEM);
        cudaFuncSetAttribute(k_agg,    cudaFuncAttributeMaxDynamicSharedMemorySize, AGG_SMEM);
        attr_set = 1;
    }

    // Launch order: k_agg is the 4th launch -> the one ncu captures.
    k_init<<<ROWS, 128>>>(h_in, out);                      // 1
    k_setup<<<4096 + 352, 256>>>(e, A, Wi, Wh);            // 2

    for (int layer = 0; layer < NLAYERS; layer++) {
        k_gemmA<<<dim3(64, 8), 256, GEMM_SMEM>>>(bh, layer == 0 ? 2 : 4);  // 3
        k_agg<<<dim3(128, 2), 256, AGG_SMEM>>>(g);                         // 4 <- profiled
        k_aggsum<<<ROWS*32/256, 256>>>();
        k_gemmWi<<<dim3(64, 3), 256, GEMM_SMEM>>>(bi);
        k_gru<<<ROWS*64/256, 256>>>();
    }

    k_readout<<<ROWS, 128>>>(Wg, bg, Wo, bo, out);
}